// round 7
// baseline (speedup 1.0000x reference)
#include <cuda_runtime.h>

#define BB 256
#define TT 512
#define VV 82
#define EE 256
#define HH 128

typedef unsigned long long u64t;

// x-projection + bias table: P[v][j], j: 0-127 f, 128-255 i, 256-383 o, 384-511 c~
__device__ __align__(16) float d_P[VV * 512];
// repacked recurrent weights: gates g in 0..2: [g][k(0..255)][j(0..127)], then c~: [k(0..127)][j]
__device__ __align__(16) float d_Wpack[3 * 256 * 128 + 128 * 128];

// SMEM-cached k-ranges
#define KC_G 96     // f/i/o gates: k in [0,96) cached
#define KC_C 112    // c~: k in [0,112) cached
#define WS_FL (3 * KC_G * 128 + KC_C * 128)   // 51200 floats cached
#define SMEM_BYTES (WS_FL * 4 + 2048 * 4 + 1536 * 4 + 1024 * 4 + 2048)  // 225280

// ---------------------------------------------------------------- helpers
__device__ __forceinline__ u64t dup2(float x) {
    u64t r;
    asm("mov.b64 %0, {%1, %1};" : "=l"(r) : "f"(x));
    return r;
}
__device__ __forceinline__ void ffma2(u64t& d, u64t a, u64t b) {
    asm("fma.rn.f32x2 %0, %1, %2, %0;" : "+l"(d) : "l"(a), "l"(b));
}
__device__ __forceinline__ float2 unpk(u64t a) {
    float2 r;
    asm("mov.b64 {%0, %1}, %2;" : "=f"(r.x), "=f"(r.y) : "l"(a));
    return r;
}
__device__ __forceinline__ float sigm(float x) {
    return 1.0f / (1.0f + __expf(-x));
}
__device__ __forceinline__ float tanh_f(float x) {
    float t = __expf(-2.0f * fabsf(x));
    float r = __fdividef(1.0f - t, 1.0f + t);
    return copysignf(r, x);
}

// ---------------------------------------------------------------- P table
__global__ void k_ptable(const float* __restrict__ emb,
                         const float* __restrict__ Wf, const float* __restrict__ Wi,
                         const float* __restrict__ Wo, const float* __restrict__ Wc,
                         const float* __restrict__ bf, const float* __restrict__ bi,
                         const float* __restrict__ bo, const float* __restrict__ bc) {
    __shared__ float se[EE];
    int v = blockIdx.x;
    int j = threadIdx.x;
    if (threadIdx.x < EE) se[threadIdx.x] = emb[v * EE + threadIdx.x];
    __syncthreads();
    const float* w;
    float b;
    if (j < 128)      { w = Wf + j * 512 + 256;         b = bf[j]; }
    else if (j < 256) { w = Wi + (j - 128) * 512 + 256; b = bi[j - 128]; }
    else if (j < 384) { w = Wo + (j - 256) * 512 + 256; b = bo[j - 256]; }
    else              { w = Wc + (j - 384) * 384 + 128; b = bc[j - 384]; }
    float a0 = 0.f, a1 = 0.f, a2 = 0.f, a3 = 0.f;
#pragma unroll 8
    for (int e = 0; e < EE; e += 4) {
        float4 wv = __ldg(reinterpret_cast<const float4*>(w + e));
        a0 += wv.x * se[e];
        a1 += wv.y * se[e + 1];
        a2 += wv.z * se[e + 2];
        a3 += wv.w * se[e + 3];
    }
    d_P[v * 512 + j] = b + ((a0 + a1) + (a2 + a3));
}

// ---------------------------------------------------------------- weight repack (transpose to [k][j])
__global__ void k_pack(const float* __restrict__ Wf, const float* __restrict__ Wi,
                       const float* __restrict__ Wo, const float* __restrict__ Wc) {
    int idx = blockIdx.x * 256 + threadIdx.x;
    if (idx < 98304) {
        int g = idx >> 15;
        int rem = idx & 32767;
        int k = rem >> 7;
        int j = rem & 127;
        const float* W = (g == 0) ? Wf : (g == 1) ? Wi : Wo;
        d_Wpack[idx] = W[j * 512 + k];   // chx recurrent columns: k<128 -> c, 128..255 -> h
    } else if (idx < 114688) {
        int r2 = idx - 98304;
        int k = r2 >> 7;
        int j = r2 & 127;
        d_Wpack[idx] = Wc[j * 384 + k];  // hx recurrent columns: k<128 -> h
    }
}

// ---------------------------------------------------------------- dot segment (warp: 2 rows, 4 j per lane)
template <int KN>
__device__ __forceinline__ void dot_seg(const float* __restrict__ wp,
                                        const float* s0r, const float* s1r,
                                        u64t* acc) {
#pragma unroll 2
    for (int k = 0; k < KN; k += 8) {
        float s0[8], s1[8];
        *(float4*)(s0)     = *(const float4*)(s0r + k);
        *(float4*)(s0 + 4) = *(const float4*)(s0r + k + 4);
        *(float4*)(s1)     = *(const float4*)(s1r + k);
        *(float4*)(s1 + 4) = *(const float4*)(s1r + k + 4);
#pragma unroll
        for (int kk = 0; kk < 8; kk++) {
            ulonglong2 wv = *(const ulonglong2*)(wp + (k + kk) * 128);
            u64t p0 = dup2(s0[kk]);
            u64t p1 = dup2(s1[kk]);
            ffma2(acc[0], wv.x, p0);
            ffma2(acc[1], wv.y, p0);
            ffma2(acc[2], wv.x, p1);
            ffma2(acc[3], wv.y, p1);
        }
    }
}

// ---------------------------------------------------------------- recurrent kernel: 64 CTAs x 256 thr, 4 rows/CTA
__global__ void __launch_bounds__(256, 1) k_recur(const int* __restrict__ reviews,
                                                  const float* __restrict__ Wcls,
                                                  const float* __restrict__ bcls,
                                                  float* __restrict__ out) {
    extern __shared__ __align__(16) float sm[];
    float* ws    = sm;                    // cached weights [WS_FL]
    float* pre   = ws + WS_FL;            // [4 gates][4 rows][128]
    float* tailb = pre + 2048;            // [3 gates][4 rows][128]
    float* st    = tailb + 1536;          // [4 rows][256] : c(0:128) | h(128:256)
    unsigned char* tok = (unsigned char*)(st + 1024);  // [4][512]

    const int tid = threadIdx.x;
    const int b0 = blockIdx.x * 4;

    // load cached weights: f/i/o k<KC_G, c~ k<KC_C
    for (int i = tid * 4; i < 3 * KC_G * 128; i += 1024) {
        int g = i / (KC_G * 128);
        int rem = i - g * (KC_G * 128);
        *(float4*)(ws + i) = *(const float4*)(d_Wpack + g * 32768 + rem);
    }
    for (int i = 3 * KC_G * 128 + tid * 4; i < WS_FL; i += 1024) {
        *(float4*)(ws + i) = *(const float4*)(d_Wpack + 98304 + (i - 3 * KC_G * 128));
    }
    // tokens (u8, vocab < 256)
    for (int i = tid; i < 4 * TT; i += 256) {
        int r = i >> 9, t = i & (TT - 1);
        tok[i] = (unsigned char)reviews[(size_t)(b0 + r) * TT + t];
    }
    for (int i = tid; i < 1024; i += 256) st[i] = 0.0f;
    __syncthreads();

    // dot-role constants
    const int w = tid >> 5, lane = tid & 31;
    const int g = w & 3;        // 0=f 1=i 2=o 3=c~+tails
    const int rp = w >> 2;
    const int r0 = rp * 2, r1 = rp * 2 + 1;
    const int jb = 4 * lane;
    const float* s0 = st + r0 * 256;
    const float* s1 = st + r1 * 256;
    const float* wsm  = ws + g * (KC_G * 128) + jb;                 // g<3
    const float* wl2  = d_Wpack + g * 32768 + KC_G * 128 + jb;      // g<3, k in [KC_G,224)
    const float* wsmc = ws + 3 * KC_G * 128 + jb;                   // c~ cached
    const float* wl2c = d_Wpack + 98304 + KC_C * 128 + jb;          // c~ k in [KC_C,128)

    // update-role constants
    const int ur = tid >> 6;
    const int uj = (tid & 63) * 2;
    float* sr = st + ur * 256;

    const size_t G = (size_t)TT * BB * HH;
    float* const outf = out + BB * VV;

    for (int t = 0; t < TT; t++) {
        // prefetch P for update role (consumed after barrier -> latency hidden)
        int v = tok[(ur << 9) + t];
        const float* Pb = d_P + v * 512 + uj;
        float2 Pf = __ldg((const float2*)(Pb));
        float2 Pi = __ldg((const float2*)(Pb + 128));
        float2 Po = __ldg((const float2*)(Pb + 256));
        float2 Pc = __ldg((const float2*)(Pb + 384));

        if (g < 3) {
            // gate g, k in [0,224): smem [0,KC_G) + L2 [KC_G,224)
            u64t acc[4] = {0, 0, 0, 0};
            dot_seg<KC_G>(wsm, s0, s1, acc);
            dot_seg<224 - KC_G>(wl2, s0 + KC_G, s1 + KC_G, acc);
            float2 a = unpk(acc[0]), b2 = unpk(acc[1]);
            *(float4*)(pre + (g * 4 + r0) * 128 + jb) = make_float4(a.x, a.y, b2.x, b2.y);
            a = unpk(acc[2]); b2 = unpk(acc[3]);
            *(float4*)(pre + (g * 4 + r1) * 128 + jb) = make_float4(a.x, a.y, b2.x, b2.y);
        } else {
            // c~ full k in [0,128): smem [0,KC_C) + L2 [KC_C,128)
            u64t acc[4] = {0, 0, 0, 0};
            dot_seg<KC_C>(wsmc, s0 + 128, s1 + 128, acc);
            dot_seg<128 - KC_C>(wl2c, s0 + 128 + KC_C, s1 + 128 + KC_C, acc);
            float2 a = unpk(acc[0]), b2 = unpk(acc[1]);
            *(float4*)(pre + (3 * 4 + r0) * 128 + jb) = make_float4(a.x, a.y, b2.x, b2.y);
            a = unpk(acc[2]); b2 = unpk(acc[3]);
            *(float4*)(pre + (3 * 4 + r1) * 128 + jb) = make_float4(a.x, a.y, b2.x, b2.y);
            // tails of f/i/o: k in [224,256) (h region of state)
#pragma unroll
            for (int gg = 0; gg < 3; gg++) {
                u64t ta[4] = {0, 0, 0, 0};
                dot_seg<32>(d_Wpack + gg * 32768 + 224 * 128 + jb, s0 + 224, s1 + 224, ta);
                float2 x = unpk(ta[0]), y = unpk(ta[1]);
                *(float4*)(tailb + (gg * 4 + r0) * 128 + jb) = make_float4(x.x, x.y, y.x, y.y);
                x = unpk(ta[2]); y = unpk(ta[3]);
                *(float4*)(tailb + (gg * 4 + r1) * 128 + jb) = make_float4(x.x, x.y, y.x, y.y);
            }
        }
        __syncthreads();

        // update phase: thread owns (row ur, j = uj, uj+1)
        {
            float2 pf = *(float2*)(pre + (0 * 4 + ur) * 128 + uj);
            float2 pi = *(float2*)(pre + (1 * 4 + ur) * 128 + uj);
            float2 po = *(float2*)(pre + (2 * 4 + ur) * 128 + uj);
            float2 pc = *(float2*)(pre + (3 * 4 + ur) * 128 + uj);
            float2 tf = *(float2*)(tailb + (0 * 4 + ur) * 128 + uj);
            float2 ti = *(float2*)(tailb + (1 * 4 + ur) * 128 + uj);
            float2 to = *(float2*)(tailb + (2 * 4 + ur) * 128 + uj);

            float f0 = sigm(pf.x + tf.x + Pf.x), f1 = sigm(pf.y + tf.y + Pf.y);
            float i0 = sigm(pi.x + ti.x + Pi.x), i1 = sigm(pi.y + ti.y + Pi.y);
            float o0 = sigm(po.x + to.x + Po.x), o1 = sigm(po.y + to.y + Po.y);
            float ct0 = tanh_f(pc.x + Pc.x),     ct1 = tanh_f(pc.y + Pc.y);

            float c0 = sr[uj], c1 = sr[uj + 1];
            float cn0 = f0 * c0 + i0 * ct0;
            float cn1 = f1 * c1 + i1 * ct1;
            float hn0 = o0 * tanh_f(cn0);
            float hn1 = o1 * tanh_f(cn1);

            size_t ob = ((size_t)t * BB + b0 + ur) * HH + uj;
            *(float2*)(outf + ob)         = make_float2(f0, f1);
            *(float2*)(outf + G + ob)     = make_float2(i0, i1);
            *(float2*)(outf + 2 * G + ob) = make_float2(o0, o1);

            sr[uj] = cn0;
            sr[uj + 1] = cn1;
            sr[128 + uj] = hn0;
            sr[128 + uj + 1] = hn1;
        }
        __syncthreads();
    }

    // classifier on final h
    for (int idx = tid; idx < 4 * VV; idx += 256) {
        int r = idx / VV, v2 = idx % VV;
        const float* hr = st + r * 256 + 128;
        const float* wr = Wcls + v2 * HH;
        float a0 = 0.f, a1 = 0.f, a2 = 0.f, a3 = 0.f;
#pragma unroll 8
        for (int j = 0; j < HH; j += 4) {
            float4 wv = __ldg(reinterpret_cast<const float4*>(wr + j));
            a0 += wv.x * hr[j];
            a1 += wv.y * hr[j + 1];
            a2 += wv.z * hr[j + 2];
            a3 += wv.w * hr[j + 3];
        }
        out[(size_t)(b0 + r) * VV + v2] = __ldg(bcls + v2) + ((a0 + a1) + (a2 + a3));
    }
}

// ---------------------------------------------------------------- launch
extern "C" void kernel_launch(void* const* d_in, const int* in_sizes, int n_in,
                              void* d_out, int out_size) {
    (void)in_sizes; (void)n_in; (void)out_size;
    const int*   reviews = (const int*)d_in[0];
    const float* emb   = (const float*)d_in[1];
    const float* Wf    = (const float*)d_in[2];
    const float* Wi    = (const float*)d_in[3];
    const float* Wo    = (const float*)d_in[4];
    const float* Wc    = (const float*)d_in[5];
    const float* bf    = (const float*)d_in[6];
    const float* bi    = (const float*)d_in[7];
    const float* bo    = (const float*)d_in[8];
    const float* bc    = (const float*)d_in[9];
    const float* Wcls  = (const float*)d_in[10];
    const float* bcls  = (const float*)d_in[11];
    float* out = (float*)d_out;

    cudaFuncSetAttribute(k_recur, cudaFuncAttributeMaxDynamicSharedMemorySize, SMEM_BYTES);

    k_ptable<<<VV, 512>>>(emb, Wf, Wi, Wo, Wc, bf, bi, bo, bc);
    k_pack<<<448, 256>>>(Wf, Wi, Wo, Wc);
    k_recur<<<BB / 4, 256, SMEM_BYTES>>>(reviews, Wcls, bcls, out);
}

// round 8
// speedup vs baseline: 2.3488x; 2.3488x over previous
#include <cuda_runtime.h>

#define BB 256
#define TT 512
#define VV 82
#define EE 256
#define HH 128

typedef unsigned long long u64t;

// x-projection + bias table: P[v][j], j: 0-127 f, 128-255 i, 256-383 o, 384-511 c~
__device__ __align__(16) float d_P[VV * 512];
// repacked recurrent weights: gates g in 0..2: [g][k(0..255)][j(0..127)], then c~: [k(0..127)][j]
__device__ __align__(16) float d_Wpack[3 * 256 * 128 + 128 * 128];

// per A-warp slot partition: 116 slots = 36 reg + 52 smem + 28 L2
#define NREG 36
#define NSM  52
#define NL2  28

// SMEM float layout
#define WS_FL   (8 * NSM * 128)   // 53248 (208 KB)
#define PART_FL (11 * 2 * 128)    // 2816
#define ST_FL   (2 * 256)         // 512
#define SMEM_BYTES ((WS_FL + PART_FL + ST_FL) * 4 + 2 * TT)  // 227328

// ---------------------------------------------------------------- helpers
__device__ __forceinline__ u64t dup2(float x) {
    u64t r;
    asm("mov.b64 %0, {%1, %1};" : "=l"(r) : "f"(x));
    return r;
}
__device__ __forceinline__ void ffma2(u64t& d, u64t a, u64t b) {
    asm("fma.rn.f32x2 %0, %1, %2, %0;" : "+l"(d) : "l"(a), "l"(b));
}
__device__ __forceinline__ float2 unpk(u64t a) {
    float2 r;
    asm("mov.b64 {%0, %1}, %2;" : "=f"(r.x), "=f"(r.y) : "l"(a));
    return r;
}
__device__ __forceinline__ float sigm(float x) {
    return 1.0f / (1.0f + __expf(-x));
}
__device__ __forceinline__ float tanh_f(float x) {
    float t = __expf(-2.0f * fabsf(x));
    float r = __fdividef(1.0f - t, 1.0f + t);
    return copysignf(r, x);
}

// ---------------------------------------------------------------- P table
__global__ void k_ptable(const float* __restrict__ emb,
                         const float* __restrict__ Wf, const float* __restrict__ Wi,
                         const float* __restrict__ Wo, const float* __restrict__ Wc,
                         const float* __restrict__ bf, const float* __restrict__ bi,
                         const float* __restrict__ bo, const float* __restrict__ bc) {
    __shared__ float se[EE];
    int v = blockIdx.x;
    int j = threadIdx.x;
    if (threadIdx.x < EE) se[threadIdx.x] = emb[v * EE + threadIdx.x];
    __syncthreads();
    const float* w;
    float b;
    if (j < 128)      { w = Wf + j * 512 + 256;         b = bf[j]; }
    else if (j < 256) { w = Wi + (j - 128) * 512 + 256; b = bi[j - 128]; }
    else if (j < 384) { w = Wo + (j - 256) * 512 + 256; b = bo[j - 256]; }
    else              { w = Wc + (j - 384) * 384 + 128; b = bc[j - 384]; }
    float a0 = 0.f, a1 = 0.f, a2 = 0.f, a3 = 0.f;
#pragma unroll 8
    for (int e = 0; e < EE; e += 4) {
        float4 wv = __ldg(reinterpret_cast<const float4*>(w + e));
        a0 += wv.x * se[e];
        a1 += wv.y * se[e + 1];
        a2 += wv.z * se[e + 2];
        a3 += wv.w * se[e + 3];
    }
    d_P[v * 512 + j] = b + ((a0 + a1) + (a2 + a3));
}

// ---------------------------------------------------------------- weight repack (transpose to [k][j])
__global__ void k_pack(const float* __restrict__ Wf, const float* __restrict__ Wi,
                       const float* __restrict__ Wo, const float* __restrict__ Wc) {
    int idx = blockIdx.x * 256 + threadIdx.x;
    if (idx < 98304) {
        int g = idx >> 15;
        int rem = idx & 32767;
        int k = rem >> 7;
        int j = rem & 127;
        const float* W = (g == 0) ? Wf : (g == 1) ? Wi : Wo;
        d_Wpack[idx] = W[j * 512 + k];   // chx recurrent columns: k<128 -> c, 128..255 -> h
    } else if (idx < 114688) {
        int r2 = idx - 98304;
        int k = r2 >> 7;
        int j = r2 & 127;
        d_Wpack[idx] = Wc[j * 384 + k];  // hx recurrent columns: k<128 -> h
    }
}

// ---------------------------------------------------------------- dot kernels (2 rows, 4 j per lane)
// register-weight dot: W indices fully constant -> stays in RF
template <int NS, int WO>
__device__ __forceinline__ void dot_reg(const u64t (&W)[2 * NREG],
                                        const float* s0r, const float* s1r, u64t* acc) {
#pragma unroll
    for (int k = 0; k < NS; k += 4) {
        float4 s0 = *(const float4*)(s0r + k);
        float4 s1 = *(const float4*)(s1r + k);
        u64t d;
        d = dup2(s0.x); ffma2(acc[0], W[WO + 2*k + 0], d); ffma2(acc[1], W[WO + 2*k + 1], d);
        d = dup2(s1.x); ffma2(acc[2], W[WO + 2*k + 0], d); ffma2(acc[3], W[WO + 2*k + 1], d);
        d = dup2(s0.y); ffma2(acc[0], W[WO + 2*k + 2], d); ffma2(acc[1], W[WO + 2*k + 3], d);
        d = dup2(s1.y); ffma2(acc[2], W[WO + 2*k + 2], d); ffma2(acc[3], W[WO + 2*k + 3], d);
        d = dup2(s0.z); ffma2(acc[0], W[WO + 2*k + 4], d); ffma2(acc[1], W[WO + 2*k + 5], d);
        d = dup2(s1.z); ffma2(acc[2], W[WO + 2*k + 4], d); ffma2(acc[3], W[WO + 2*k + 5], d);
        d = dup2(s0.w); ffma2(acc[0], W[WO + 2*k + 6], d); ffma2(acc[1], W[WO + 2*k + 7], d);
        d = dup2(s1.w); ffma2(acc[2], W[WO + 2*k + 6], d); ffma2(acc[3], W[WO + 2*k + 7], d);
    }
}

// pointer-weight dot (SMEM), stride 128 floats per slot, wp already +jb
template <int KN>
__device__ __forceinline__ void dot_ptr(const float* __restrict__ wp,
                                        const float* s0r, const float* s1r, u64t* acc) {
#pragma unroll
    for (int k = 0; k < KN; k += 4) {
        float4 s0 = *(const float4*)(s0r + k);
        float4 s1 = *(const float4*)(s1r + k);
        ulonglong2 w0 = *(const ulonglong2*)(wp + (k + 0) * 128);
        ulonglong2 w1 = *(const ulonglong2*)(wp + (k + 1) * 128);
        ulonglong2 w2 = *(const ulonglong2*)(wp + (k + 2) * 128);
        ulonglong2 w3 = *(const ulonglong2*)(wp + (k + 3) * 128);
        u64t d;
        d = dup2(s0.x); ffma2(acc[0], w0.x, d); ffma2(acc[1], w0.y, d);
        d = dup2(s1.x); ffma2(acc[2], w0.x, d); ffma2(acc[3], w0.y, d);
        d = dup2(s0.y); ffma2(acc[0], w1.x, d); ffma2(acc[1], w1.y, d);
        d = dup2(s1.y); ffma2(acc[2], w1.x, d); ffma2(acc[3], w1.y, d);
        d = dup2(s0.z); ffma2(acc[0], w2.x, d); ffma2(acc[1], w2.y, d);
        d = dup2(s1.z); ffma2(acc[2], w2.x, d); ffma2(acc[3], w2.y, d);
        d = dup2(s0.w); ffma2(acc[0], w3.x, d); ffma2(acc[1], w3.y, d);
        d = dup2(s1.w); ffma2(acc[2], w3.x, d); ffma2(acc[3], w3.y, d);
    }
}

// consume an L2-prefetched batch held in registers
template <int NB>
__device__ __forceinline__ void consumeL(const ulonglong2* L,
                                         const float* s0r, const float* s1r, u64t* acc) {
#pragma unroll
    for (int k = 0; k < NB; k += 4) {
        float4 s0 = *(const float4*)(s0r + k);
        float4 s1 = *(const float4*)(s1r + k);
        u64t d;
        d = dup2(s0.x); ffma2(acc[0], L[k + 0].x, d); ffma2(acc[1], L[k + 0].y, d);
        d = dup2(s1.x); ffma2(acc[2], L[k + 0].x, d); ffma2(acc[3], L[k + 0].y, d);
        d = dup2(s0.y); ffma2(acc[0], L[k + 1].x, d); ffma2(acc[1], L[k + 1].y, d);
        d = dup2(s1.y); ffma2(acc[2], L[k + 1].x, d); ffma2(acc[3], L[k + 1].y, d);
        d = dup2(s0.z); ffma2(acc[0], L[k + 2].x, d); ffma2(acc[1], L[k + 2].y, d);
        d = dup2(s1.z); ffma2(acc[2], L[k + 2].x, d); ffma2(acc[3], L[k + 2].y, d);
        d = dup2(s0.w); ffma2(acc[0], L[k + 3].x, d); ffma2(acc[1], L[k + 3].y, d);
        d = dup2(s1.w); ffma2(acc[2], L[k + 3].x, d); ffma2(acc[3], L[k + 3].y, d);
    }
}

__device__ __forceinline__ void store_part(float* part, int pbuf, int jb, const u64t* acc) {
    float2 a = unpk(acc[0]), b = unpk(acc[1]);
    *(float4*)(part + (pbuf * 2 + 0) * 128 + jb) = make_float4(a.x, a.y, b.x, b.y);
    a = unpk(acc[2]); b = unpk(acc[3]);
    *(float4*)(part + (pbuf * 2 + 1) * 128 + jb) = make_float4(a.x, a.y, b.x, b.y);
}

// ---------------------------------------------------------------- recurrent kernel: 128 CTAs x 256 thr, 2 rows/CTA
// Warp roles (k-slot partition of the 896 total k-slots):
//   w0: f[0,116)   w1: f[116,232)   w2: i[0,116)  w3: i[116,232)
//   w4: o[0,116)   w5: o[116,232)   w6: c[0,116)
//   w7: c[116,128) + f[232,256) + i[232,256) + o[232,256)
// A-warps: 36 reg + 52 smem + 28 L2.  w7: reg = c12+f24, smem = i24+o24.
__global__ void __launch_bounds__(256, 1) k_recur(const int* __restrict__ reviews,
                                                  const float* __restrict__ Wcls,
                                                  const float* __restrict__ bcls,
                                                  float* __restrict__ out) {
    extern __shared__ __align__(16) float sm[];
    float* ws   = sm;                  // [8][NSM*128]
    float* part = ws + WS_FL;          // [11][2][128]
    float* st   = part + PART_FL;      // [2][256]: c(0:128)|h(128:256)
    unsigned char* tok = (unsigned char*)(st + ST_FL);  // [2][512]

    const int tid = threadIdx.x;
    const int w = tid >> 5, lane = tid & 31;
    const int jb = 4 * lane;
    const int b0 = blockIdx.x * 2;

    // ---- per-warp config (A-warps)
    const int g = w >> 1;                  // w6 -> 3 (c~)
    const int k0 = (w & 1) * 116;
    const int gbase = (g < 3) ? g * 32768 : 98304;
    const int wr_off = gbase + k0 * 128;
    const int sbase = ((g < 3) ? 0 : 128) + k0;
    const int pbuf = g * 3 + (w & 1);

    // ---- fill SMEM weight regions
    if (w < 7) {
        const float* src = d_Wpack + wr_off + NREG * 128 + jb;
        float* dst = ws + w * (NSM * 128) + jb;
        for (int s = 0; s < NSM; s++)
            *(float4*)(dst + s * 128) = *(const float4*)(src + s * 128);
    } else {
        float* dst = ws + 7 * (NSM * 128) + jb;
        const float* si = d_Wpack + 32768 + 232 * 128 + jb;   // i[232,256)
        const float* so = d_Wpack + 65536 + 232 * 128 + jb;   // o[232,256)
        for (int s = 0; s < 24; s++) {
            *(float4*)(dst + s * 128)        = *(const float4*)(si + s * 128);
            *(float4*)(dst + (24 + s) * 128) = *(const float4*)(so + s * 128);
        }
    }

    // ---- load register weights
    u64t Wr[2 * NREG];
    if (w < 7) {
        const float* src = d_Wpack + wr_off + jb;
#pragma unroll
        for (int s = 0; s < NREG; s++) {
            ulonglong2 v = *(const ulonglong2*)(src + s * 128);
            Wr[2 * s] = v.x; Wr[2 * s + 1] = v.y;
        }
    } else {
        const float* sc = d_Wpack + 98304 + 116 * 128 + jb;   // c[116,128): 12 slots
        const float* sf = d_Wpack + 232 * 128 + jb;           // f[232,256): 24 slots
#pragma unroll
        for (int s = 0; s < 12; s++) {
            ulonglong2 v = *(const ulonglong2*)(sc + s * 128);
            Wr[2 * s] = v.x; Wr[2 * s + 1] = v.y;
        }
#pragma unroll
        for (int s = 0; s < 24; s++) {
            ulonglong2 v = *(const ulonglong2*)(sf + s * 128);
            Wr[24 + 2 * s] = v.x; Wr[24 + 2 * s + 1] = v.y;
        }
    }

    // ---- tokens + state init
    for (int i = tid; i < 2 * TT; i += 256) {
        int r = i >> 9, t = i & (TT - 1);
        tok[i] = (unsigned char)reviews[(size_t)(b0 + r) * TT + t];
    }
    for (int i = tid; i < ST_FL; i += 256) st[i] = 0.0f;
    __syncthreads();

    const float* st0 = st;
    const float* st1 = st + 256;
    const float* wsm  = ws + w * (NSM * 128) + jb;            // A: slots [36,88)
    const float* wl2p = d_Wpack + wr_off + 88 * 128 + jb;     // A: slots [88,116)
    const float* wsB  = ws + 7 * (NSM * 128) + jb;            // w7 region

    // update-role constants
    const int ur = tid >> 7;          // row 0/1
    const int uj = tid & 127;         // j
    float* str = st + ur * 256;

    const size_t G = (size_t)TT * BB * HH;
    float* const outf = out + BB * VV;

    for (int t = 0; t < TT; t++) {
        // P prefetch (consumed after the barrier)
        int v = tok[(ur << 9) + t];
        const float* Pb = d_P + v * 512 + uj;
        float Pf = __ldg(Pb);
        float Pi = __ldg(Pb + 128);
        float Po = __ldg(Pb + 256);
        float Pc = __ldg(Pb + 384);

        if (w < 7) {
            u64t acc[4] = {0, 0, 0, 0};
            ulonglong2 L[8];
            const float* sb0 = st0 + sbase;
            const float* sb1 = st1 + sbase;
            // batch 0: L2 slots [88,96)
#pragma unroll
            for (int s = 0; s < 8; s++) L[s] = *(const ulonglong2*)(wl2p + s * 128);
            dot_reg<NREG, 0>(Wr, sb0, sb1, acc);
            consumeL<8>(L, sb0 + 88, sb1 + 88, acc);
#pragma unroll
            for (int s = 0; s < 8; s++) L[s] = *(const ulonglong2*)(wl2p + (8 + s) * 128);
            dot_ptr<20>(wsm, sb0 + 36, sb1 + 36, acc);
            consumeL<8>(L, sb0 + 96, sb1 + 96, acc);
#pragma unroll
            for (int s = 0; s < 8; s++) L[s] = *(const ulonglong2*)(wl2p + (16 + s) * 128);
            dot_ptr<20>(wsm + 20 * 128, sb0 + 56, sb1 + 56, acc);
            consumeL<8>(L, sb0 + 104, sb1 + 104, acc);
#pragma unroll
            for (int s = 0; s < 4; s++) L[s] = *(const ulonglong2*)(wl2p + (24 + s) * 128);
            dot_ptr<12>(wsm + 40 * 128, sb0 + 76, sb1 + 76, acc);
            consumeL<4>(L, sb0 + 112, sb1 + 112, acc);
            store_part(part, pbuf, jb, acc);
        } else {
            u64t acc[4];
            // c~[116,128): reg, state 244
            acc[0] = acc[1] = acc[2] = acc[3] = 0;
            dot_reg<12, 0>(Wr, st0 + 244, st1 + 244, acc);
            store_part(part, 10, jb, acc);
            // f[232,256): reg, state 232
            acc[0] = acc[1] = acc[2] = acc[3] = 0;
            dot_reg<24, 24>(Wr, st0 + 232, st1 + 232, acc);
            store_part(part, 2, jb, acc);
            // i[232,256): smem
            acc[0] = acc[1] = acc[2] = acc[3] = 0;
            dot_ptr<24>(wsB, st0 + 232, st1 + 232, acc);
            store_part(part, 5, jb, acc);
            // o[232,256): smem
            acc[0] = acc[1] = acc[2] = acc[3] = 0;
            dot_ptr<24>(wsB + 24 * 128, st0 + 232, st1 + 232, acc);
            store_part(part, 8, jb, acc);
        }
        __syncthreads();

        // update phase: thread owns (row ur, col uj)
        {
            const float* p = part + ur * 128 + uj;
            float pf = p[0 * 256] + p[1 * 256] + p[2 * 256] + Pf;
            float pi = p[3 * 256] + p[4 * 256] + p[5 * 256] + Pi;
            float po = p[6 * 256] + p[7 * 256] + p[8 * 256] + Po;
            float pc = p[9 * 256] + p[10 * 256] + Pc;

            float f  = sigm(pf);
            float ii = sigm(pi);
            float o  = sigm(po);
            float ct = tanh_f(pc);

            float c  = str[uj];
            float cn = f * c + ii * ct;
            float hn = o * tanh_f(cn);
            str[uj] = cn;
            str[128 + uj] = hn;

            size_t ob = ((size_t)t * BB + b0 + ur) * HH + uj;
            outf[ob]         = f;
            outf[G + ob]     = ii;
            outf[2 * G + ob] = o;
        }
        __syncthreads();
    }

    // classifier on final h
    for (int idx = tid; idx < 2 * VV; idx += 256) {
        int r = idx / VV, v2 = idx % VV;
        const float* hr = st + r * 256 + 128;
        const float* wr = Wcls + v2 * HH;
        float a0 = 0.f, a1 = 0.f, a2 = 0.f, a3 = 0.f;
#pragma unroll 8
        for (int j = 0; j < HH; j += 4) {
            float4 wv = __ldg(reinterpret_cast<const float4*>(wr + j));
            a0 += wv.x * hr[j];
            a1 += wv.y * hr[j + 1];
            a2 += wv.z * hr[j + 2];
            a3 += wv.w * hr[j + 3];
        }
        out[(size_t)(b0 + r) * VV + v2] = __ldg(bcls + v2) + ((a0 + a1) + (a2 + a3));
    }
}

// ---------------------------------------------------------------- launch
extern "C" void kernel_launch(void* const* d_in, const int* in_sizes, int n_in,
                              void* d_out, int out_size) {
    (void)in_sizes; (void)n_in; (void)out_size;
    const int*   reviews = (const int*)d_in[0];
    const float* emb   = (const float*)d_in[1];
    const float* Wf    = (const float*)d_in[2];
    const float* Wi    = (const float*)d_in[3];
    const float* Wo    = (const float*)d_in[4];
    const float* Wc    = (const float*)d_in[5];
    const float* bf    = (const float*)d_in[6];
    const float* bi    = (const float*)d_in[7];
    const float* bo    = (const float*)d_in[8];
    const float* bc    = (const float*)d_in[9];
    const float* Wcls  = (const float*)d_in[10];
    const float* bcls  = (const float*)d_in[11];
    float* out = (float*)d_out;

    cudaFuncSetAttribute(k_recur, cudaFuncAttributeMaxDynamicSharedMemorySize, SMEM_BYTES);

    k_ptable<<<VV, 512>>>(emb, Wf, Wi, Wo, Wc, bf, bi, bo, bc);
    k_pack<<<448, 256>>>(Wf, Wi, Wo, Wc);
    k_recur<<<BB / 2, 256, SMEM_BYTES>>>(reviews, Wcls, bcls, out);
}